// round 17
// baseline (speedup 1.0000x reference)
#include <cuda_runtime.h>
#include <cuda_bf16.h>

// Problem constants (fixed shapes)
#define NB   2
#define NQL  4096
#define NKL  4096
#define NQD  512
#define NCD  768
#define NH   8
#define NDH  64
#define NIN  512            // H * DH
#define ATTN_SCALE 0.125f   // DH^-0.5

// Scratch (static device globals -- allocation-free per harness rules)
__device__ __nv_bfloat16 g_Xh[NB * NQL * NQD];
__device__ __nv_bfloat16 g_Xl[NB * NQL * NQD];
__device__ __nv_bfloat16 g_Ch[NB * NKL * NCD];
__device__ __nv_bfloat16 g_Cl[NB * NKL * NCD];
__device__ __nv_bfloat16 g_Qh[NB * NQL * NIN];
__device__ __nv_bfloat16 g_Ql[NB * NQL * NIN];
__device__ __nv_bfloat16 g_Kh[NB * NKL * NIN];
__device__ __nv_bfloat16 g_Kl[NB * NKL * NIN];
__device__ __nv_bfloat16 g_Vh[NB * NKL * NIN];   // transposed: [b][h][d][k]
__device__ __nv_bfloat16 g_Vl[NB * NKL * NIN];
__device__ __nv_bfloat16 g_Oh[NB * NQL * NIN];
__device__ __nv_bfloat16 g_Ol[NB * NQL * NIN];
__device__ __nv_bfloat16 g_Wqh[NQD * NIN];       // all weights transposed: [N][K]
__device__ __nv_bfloat16 g_Wql[NQD * NIN];
__device__ __nv_bfloat16 g_Wkh[NCD * NIN];
__device__ __nv_bfloat16 g_Wkl[NCD * NIN];
__device__ __nv_bfloat16 g_Wvh[NCD * NIN];
__device__ __nv_bfloat16 g_Wvl[NCD * NIN];
__device__ __nv_bfloat16 g_Woh[NIN * NQD];
__device__ __nv_bfloat16 g_Wol[NIN * NQD];

// ---------------------------------------------------------------------------
// Primitive helpers
// ---------------------------------------------------------------------------
__device__ __forceinline__ void mma_bf16(float d[4], const unsigned a[4],
                                         unsigned b0, unsigned b1)
{
    asm volatile(
        "mma.sync.aligned.m16n8k16.row.col.f32.bf16.bf16.f32 "
        "{%0,%1,%2,%3}, {%4,%5,%6,%7}, {%8,%9}, {%0,%1,%2,%3};"
        : "+f"(d[0]), "+f"(d[1]), "+f"(d[2]), "+f"(d[3])
        : "r"(a[0]), "r"(a[1]), "r"(a[2]), "r"(a[3]), "r"(b0), "r"(b1));
}

__device__ __forceinline__ void split1(float v, __nv_bfloat16& h, __nv_bfloat16& l)
{
    h = __float2bfloat16(v);
    l = __float2bfloat16(v - __bfloat162float(h));
}

__device__ __forceinline__ unsigned s2u(const void* p)
{
    return (unsigned)__cvta_generic_to_shared(p);
}

__device__ __forceinline__ void ldm_x4(unsigned r[4], unsigned addr)
{
    asm volatile("ldmatrix.sync.aligned.m8n8.x4.shared.b16 {%0,%1,%2,%3}, [%4];"
                 : "=r"(r[0]), "=r"(r[1]), "=r"(r[2]), "=r"(r[3]) : "r"(addr));
}

__device__ __forceinline__ void cp16(void* dst, const void* src)
{
    unsigned d = s2u(dst);
    asm volatile("cp.async.cg.shared.global [%0], [%1], 16;" :: "r"(d), "l"(src));
}
#define CP_COMMIT() asm volatile("cp.async.commit_group;")
#define CP_WAIT(N)  asm volatile("cp.async.wait_group %0;" :: "n"(N))

// ---------------------------------------------------------------------------
// fp32 -> bf16 hi/lo split (elementwise), float4-vectorized
// ---------------------------------------------------------------------------
__global__ __launch_bounds__(256) void split_kernel(
    const float* __restrict__ in, __nv_bfloat16* __restrict__ hi,
    __nv_bfloat16* __restrict__ lo, int n4)
{
    int i = blockIdx.x * 256 + threadIdx.x;
    if (i >= n4) return;
    float4 v = ((const float4*)in)[i];
    float f[4] = {v.x, v.y, v.z, v.w};
    __nv_bfloat162 H0, H1, L0, L1;
    split1(f[0], H0.x, L0.x); split1(f[1], H0.y, L0.y);
    split1(f[2], H1.x, L1.x); split1(f[3], H1.y, L1.y);
    uint2 uh, ul;
    uh.x = *(unsigned*)&H0; uh.y = *(unsigned*)&H1;
    ul.x = *(unsigned*)&L0; ul.y = *(unsigned*)&L1;
    ((uint2*)hi)[i] = uh;
    ((uint2*)lo)[i] = ul;
}

// ---------------------------------------------------------------------------
// Weight transpose + split: W[K][N] fp32 -> Wt[N][K] bf16 hi/lo
// ---------------------------------------------------------------------------
__global__ __launch_bounds__(256) void wsplit_kernel(
    const float* __restrict__ W, __nv_bfloat16* __restrict__ wh,
    __nv_bfloat16* __restrict__ wl, int K, int N)
{
    __shared__ float tile[32][33];
    const int k0 = blockIdx.x * 32, n0 = blockIdx.y * 32;
    for (int yy = threadIdx.y; yy < 32; yy += 8)
        tile[yy][threadIdx.x] = W[(long)(k0 + yy) * N + n0 + threadIdx.x];
    __syncthreads();
    for (int yy = threadIdx.y; yy < 32; yy += 8) {
        float x = tile[threadIdx.x][yy];      // = W[k0+tx][n0+yy]
        long o = (long)(n0 + yy) * K + k0 + threadIdx.x;
        __nv_bfloat16 hh, ll;
        split1(x, hh, ll);
        wh[o] = hh; wl[o] = ll;
    }
}

// ---------------------------------------------------------------------------
// bf16x3 GEMM on mma.sync: C[M,N] = (Ah+Al)[M,K] @ (Bh+Bl)[N,K]^T
// 128x128 tile, BK=32, 256 threads = 8 warps (4m x 2n slabs), warp 32m x 64n.
// cp.async 2-stage double buffer; ldmatrix.x4 fragment loads.
// Rows padded to 40 bf16 (pitch 80B) -> conflict-free LDSM.
// MODE 0: Cf = acc + bias (fp32). MODE 1: bf16 hi/lo split of acc*scale.
// MODE 2: V-transposed split -> [b][h][d][k].
// ---------------------------------------------------------------------------
#define G3_TS   (128 * 40)            // elems per array per stage
#define G3_SMEM (2 * 4 * G3_TS * 2)   // bytes: 81920

#define G3_LOAD(st, k0) do {                                                  \
    __nv_bfloat16* p = smp + (st) * 4 * G3_TS;                                \
    _Pragma("unroll")                                                         \
    for (int i_ = 0; i_ < 2; i_++) {                                          \
        int r_ = lr + 64 * i_;                                                \
        long ao_ = (long)(mBlk + r_) * K + (k0) + lc;                         \
        long bo_ = (long)(nBlk + r_) * K + (k0) + lc;                         \
        cp16(p + r_ * 40 + lc,              Ah + ao_);                        \
        cp16(p + G3_TS + r_ * 40 + lc,      Al + ao_);                        \
        cp16(p + 2 * G3_TS + r_ * 40 + lc,  Bh + bo_);                        \
        cp16(p + 3 * G3_TS + r_ * 40 + lc,  Bl + bo_);                        \
    }                                                                         \
    CP_COMMIT(); } while (0)

template <int MODE>
__global__ __launch_bounds__(256) void gemm3_kernel(
    const __nv_bfloat16* __restrict__ Ah, const __nv_bfloat16* __restrict__ Al,
    const __nv_bfloat16* __restrict__ Bh, const __nv_bfloat16* __restrict__ Bl,
    const float* __restrict__ bias, float* __restrict__ Cf,
    __nv_bfloat16* __restrict__ Ch, __nv_bfloat16* __restrict__ Cl,
    int M, int N, int K, float scale)
{
    extern __shared__ __align__(16) char dynsmem[];
    __nv_bfloat16* smp = (__nv_bfloat16*)dynsmem;

    const int tid  = threadIdx.x;
    const int lane = tid & 31;
    const int w    = tid >> 5;
    const int g    = lane >> 2;
    const int t    = lane & 3;
    const int wm   = w & 3;     // m-slab (32 rows)
    const int wn   = w >> 2;    // n-slab (64 cols)

    const int mBlk = blockIdx.y << 7;
    const int nBlk = blockIdx.x << 7;

    // ldmatrix per-lane intra-fragment byte offsets (pitch 40 bf16 = 80 B)
    const unsigned lrow = lane & 7, lsel = lane >> 3;
    const unsigned fragA = ((lrow + 8 * (lsel & 1)) * 40 + 8 * (lsel >> 1)) * 2;
    const unsigned fragB = ((lrow + 8 * (lsel >> 1)) * 40 + 8 * (lsel & 1)) * 2;
    const unsigned base_u = s2u(smp);

    // cp.async load indexing
    const int lr = tid >> 2;            // 0..63
    const int lc = (tid & 3) << 3;      // 0,8,16,24

    float acc[2][8][4];
#pragma unroll
    for (int mt = 0; mt < 2; mt++)
#pragma unroll
        for (int nt = 0; nt < 8; nt++)
#pragma unroll
            for (int e = 0; e < 4; e++) acc[mt][nt][e] = 0.f;

    const int NKI = K >> 5;
    G3_LOAD(0, 0);

    for (int i = 0; i < NKI; i++) {
        if (i + 1 < NKI) { G3_LOAD((i + 1) & 1, (i + 1) * 32); CP_WAIT(1); }
        else             { CP_WAIT(0); }
        __syncthreads();

        const unsigned sb = base_u + (unsigned)(i & 1) * (4 * G3_TS * 2);
#pragma unroll
        for (int ks = 0; ks < 2; ks++) {
            const unsigned aoff = sb + ((wm * 32) * 40 + 16 * ks) * 2;
            unsigned afh[2][4], afl[2][4];
            ldm_x4(afh[0], aoff + fragA);
            ldm_x4(afh[1], aoff + 16 * 40 * 2 + fragA);
            ldm_x4(afl[0], aoff + G3_TS * 2 + fragA);
            ldm_x4(afl[1], aoff + G3_TS * 2 + 16 * 40 * 2 + fragA);
#pragma unroll
            for (int ntp = 0; ntp < 4; ntp++) {
                const unsigned boff =
                    sb + 2 * G3_TS * 2 + ((wn * 64 + ntp * 16) * 40 + 16 * ks) * 2;
                unsigned bh[4], bl[4];
                ldm_x4(bh, boff + fragB);
                ldm_x4(bl, boff + G3_TS * 2 + fragB);
#pragma unroll
                for (int mt = 0; mt < 2; mt++) {
                    mma_bf16(acc[mt][2 * ntp],     afh[mt], bh[0], bh[1]);
                    mma_bf16(acc[mt][2 * ntp],     afh[mt], bl[0], bl[1]);
                    mma_bf16(acc[mt][2 * ntp],     afl[mt], bh[0], bh[1]);
                    mma_bf16(acc[mt][2 * ntp + 1], afh[mt], bh[2], bh[3]);
                    mma_bf16(acc[mt][2 * ntp + 1], afh[mt], bl[2], bl[3]);
                    mma_bf16(acc[mt][2 * ntp + 1], afl[mt], bh[2], bh[3]);
                }
            }
        }
        __syncthreads();
    }

    // ---- epilogue ----
#pragma unroll
    for (int mt = 0; mt < 2; mt++) {
#pragma unroll
        for (int nt = 0; nt < 8; nt++) {
            int r0 = mBlk + wm * 32 + mt * 16 + g;
            int cb = nBlk + wn * 64 + nt * 8 + 2 * t;
#pragma unroll
            for (int half = 0; half < 2; half++) {
                int row = r0 + 8 * half;
                float v0 = acc[mt][nt][2 * half];
                float v1 = acc[mt][nt][2 * half + 1];
                if (MODE == 0) {
                    float2 o;
                    o.x = v0 + bias[cb];
                    o.y = v1 + bias[cb + 1];
                    *(float2*)(Cf + (long)row * N + cb) = o;
                } else if (MODE == 1) {
                    __nv_bfloat162 H, L;
                    split1(v0 * scale, H.x, L.x);
                    split1(v1 * scale, H.y, L.y);
                    long o = (long)row * N + cb;
                    *(__nv_bfloat162*)(Ch + o) = H;
                    *(__nv_bfloat162*)(Cl + o) = L;
                } else {   // MODE 2: V transposed per head -> [b][h][d][k]
                    int b = row >> 12, k = row & 4095;
#pragma unroll
                    for (int e = 0; e < 2; e++) {
                        int col = cb + e;
                        int hh = col >> 6, d = col & 63;
                        long o = (((long)(b * NH + hh) * NDH + d) * NKL) + k;
                        float v = e ? v1 : v0;
                        __nv_bfloat16 vh, vl;
                        split1(v, vh, vl);
                        Ch[o] = vh; Cl[o] = vl;
                    }
                }
            }
        }
    }
}

// ---------------------------------------------------------------------------
// bf16-split flash attention on mma.sync.m16n8k16.
// Block = 128 queries of one (b,h); 256 threads = 8 warps x 16-q slabs.
// (q-tile doubled vs R14: halves L2-resident K/V re-read traffic.)
// cp.async 2-stage double buffer for 64-key K/V tiles; ldmatrix.x4 loads.
// Rows padded to 72 bf16 (144B pitch) -> conflict-free LDSM.
// ---------------------------------------------------------------------------
#define AT_AS   (64 * 72)             // elems per array per stage
#define AT_SMEM (2 * 4 * AT_AS * 2)   // bytes: 73728

#define AT_LOAD(st, kt) do {                                                  \
    __nv_bfloat16* p = smp + (st) * 4 * AT_AS;                                \
    _Pragma("unroll")                                                         \
    for (int i_ = 0; i_ < 2; i_++) {                                          \
        int r_ = lr + 32 * i_;                                                \
        long ko_ = (long)((kt) * 64 + r_) * NIN + lc;                         \
        long vo_ = (long)r_ * NKL + (kt) * 64 + lc;                           \
        cp16(p + r_ * 72 + lc,              kbh + ko_);                       \
        cp16(p + AT_AS + r_ * 72 + lc,      kbl + ko_);                       \
        cp16(p + 2 * AT_AS + r_ * 72 + lc,  vbh + vo_);                       \
        cp16(p + 3 * AT_AS + r_ * 72 + lc,  vbl + vo_);                       \
    }                                                                         \
    CP_COMMIT(); } while (0)

__global__ __launch_bounds__(256) void attn_mma_kernel(
    const __nv_bfloat16* __restrict__ Qh, const __nv_bfloat16* __restrict__ Ql,
    const __nv_bfloat16* __restrict__ Kh, const __nv_bfloat16* __restrict__ Kl,
    const __nv_bfloat16* __restrict__ Vh, const __nv_bfloat16* __restrict__ Vl,
    __nv_bfloat16* __restrict__ Oh, __nv_bfloat16* __restrict__ Ol)
{
    extern __shared__ __align__(16) char dynsmem[];
    __nv_bfloat16* smp = (__nv_bfloat16*)dynsmem;

    const int tid  = threadIdx.x;
    const int lane = tid & 31;
    const int w    = tid >> 5;     // 0..7: 16-q slab within the 128-q tile
    const int g    = lane >> 2;
    const int t    = lane & 3;

    const int qt = blockIdx.x, h = blockIdx.y, b = blockIdx.z;

    const unsigned lrow = lane & 7, lsel = lane >> 3;
    const unsigned frag = (lrow * 72 + 8 * lsel) * 2;   // pitch 72 bf16 = 144 B
    const unsigned base_u = s2u(smp);

    const int lr = tid >> 3;            // 0..31
    const int lc = (tid & 7) << 3;      // 0..56

    // ---- Q fragments in registers (constant across key loop) ----
    unsigned qfh[4][4], qfl[4][4];
    {
        const long qoff = ((long)(b * NQL + qt * 128 + w * 16)) * NIN + h * NDH;
        const __nv_bfloat16* qh = Qh + qoff;
        const __nv_bfloat16* ql = Ql + qoff;
#pragma unroll
        for (int j = 0; j < 4; j++) {
            int d0 = 16 * j + 2 * t;
            qfh[j][0] = *(const unsigned*)(qh + (long)g * NIN + d0);
            qfh[j][1] = *(const unsigned*)(qh + (long)(g + 8) * NIN + d0);
            qfh[j][2] = *(const unsigned*)(qh + (long)g * NIN + d0 + 8);
            qfh[j][3] = *(const unsigned*)(qh + (long)(g + 8) * NIN + d0 + 8);
            qfl[j][0] = *(const unsigned*)(ql + (long)g * NIN + d0);
            qfl[j][1] = *(const unsigned*)(ql + (long)(g + 8) * NIN + d0);
            qfl[j][2] = *(const unsigned*)(ql + (long)g * NIN + d0 + 8);
            qfl[j][3] = *(const unsigned*)(ql + (long)(g + 8) * NIN + d0 + 8);
        }
    }

    float o[8][4];
#pragma unroll
    for (int ct = 0; ct < 8; ct++)
#pragma unroll
        for (int e = 0; e < 4; e++) o[ct][e] = 0.f;
    float m0 = -1e30f, m1 = -1e30f, l0 = 0.f, l1 = 0.f;

    const __nv_bfloat16* kbh = Kh + (long)b * NKL * NIN + h * NDH;
    const __nv_bfloat16* kbl = Kl + (long)b * NKL * NIN + h * NDH;
    const __nv_bfloat16* vbh = Vh + (long)(b * NH + h) * NDH * NKL;
    const __nv_bfloat16* vbl = Vl + (long)(b * NH + h) * NDH * NKL;

    const int NKT = NKL / 64;
    AT_LOAD(0, 0);

    for (int kt = 0; kt < NKT; kt++) {
        if (kt + 1 < NKT) { AT_LOAD((kt + 1) & 1, kt + 1); CP_WAIT(1); }
        else              { CP_WAIT(0); }
        __syncthreads();

        const unsigned sb = base_u + (unsigned)(kt & 1) * (4 * AT_AS * 2);

        // ---- S = Q @ K^T (bf16x3) via ldmatrix.x4 ----
        float s[8][4];
#pragma unroll
        for (int nt = 0; nt < 8; nt++) {
            s[nt][0] = s[nt][1] = s[nt][2] = s[nt][3] = 0.f;
#pragma unroll
            for (int jp = 0; jp < 2; jp++) {
                const unsigned ka = sb + nt * 1152 + jp * 64 + frag;
                unsigned bh[4], bl[4];
                ldm_x4(bh, ka);
                ldm_x4(bl, ka + AT_AS * 2);
                mma_bf16(s[nt], qfh[2 * jp],     bh[0], bh[1]);
                mma_bf16(s[nt], qfh[2 * jp],     bl[0], bl[1]);
                mma_bf16(s[nt], qfl[2 * jp],     bh[0], bh[1]);
                mma_bf16(s[nt], qfh[2 * jp + 1], bh[2], bh[3]);
                mma_bf16(s[nt], qfh[2 * jp + 1], bl[2], bl[3]);
                mma_bf16(s[nt], qfl[2 * jp + 1], bh[2], bh[3]);
            }
        }

        // ---- online softmax ----
        float mt0 = -1e30f, mt1 = -1e30f;
#pragma unroll
        for (int nt = 0; nt < 8; nt++) {
            mt0 = fmaxf(mt0, fmaxf(s[nt][0], s[nt][1]));
            mt1 = fmaxf(mt1, fmaxf(s[nt][2], s[nt][3]));
        }
        mt0 = fmaxf(mt0, __shfl_xor_sync(0xffffffffu, mt0, 1));
        mt0 = fmaxf(mt0, __shfl_xor_sync(0xffffffffu, mt0, 2));
        mt1 = fmaxf(mt1, __shfl_xor_sync(0xffffffffu, mt1, 1));
        mt1 = fmaxf(mt1, __shfl_xor_sync(0xffffffffu, mt1, 2));
        float mn0 = fmaxf(m0, mt0), mn1 = fmaxf(m1, mt1);
        float cr0 = __expf(m0 - mn0), cr1 = __expf(m1 - mn1);
        m0 = mn0; m1 = mn1;

        float rs0 = 0.f, rs1 = 0.f;
        unsigned ph[8][2], pl[8][2];
#pragma unroll
        for (int nt = 0; nt < 8; nt++) {
            float p0 = __expf(s[nt][0] - m0), p1 = __expf(s[nt][1] - m0);
            float p2 = __expf(s[nt][2] - m1), p3 = __expf(s[nt][3] - m1);
            rs0 += p0 + p1; rs1 += p2 + p3;
            __nv_bfloat162 H, L;
            split1(p0, H.x, L.x); split1(p1, H.y, L.y);
            ph[nt][0] = *(unsigned*)&H; pl[nt][0] = *(unsigned*)&L;
            split1(p2, H.x, L.x); split1(p3, H.y, L.y);
            ph[nt][1] = *(unsigned*)&H; pl[nt][1] = *(unsigned*)&L;
        }
        rs0 += __shfl_xor_sync(0xffffffffu, rs0, 1);
        rs0 += __shfl_xor_sync(0xffffffffu, rs0, 2);
        rs1 += __shfl_xor_sync(0xffffffffu, rs1, 1);
        rs1 += __shfl_xor_sync(0xffffffffu, rs1, 2);
        l0 = l0 * cr0 + rs0;
        l1 = l1 * cr1 + rs1;
#pragma unroll
        for (int ct = 0; ct < 8; ct++) {
            o[ct][0] *= cr0; o[ct][1] *= cr0;
            o[ct][2] *= cr1; o[ct][3] *= cr1;
        }

        // ---- O += P @ V (bf16x3) via ldmatrix.x4 ----
#pragma unroll
        for (int jp = 0; jp < 2; jp++) {
            unsigned ah0[4] = {ph[4 * jp][0],     ph[4 * jp][1],
                               ph[4 * jp + 1][0], ph[4 * jp + 1][1]};
            unsigned al0[4] = {pl[4 * jp][0],     pl[4 * jp][1],
                               pl[4 * jp + 1][0], pl[4 * jp + 1][1]};
            unsigned ah1[4] = {ph[4 * jp + 2][0], ph[4 * jp + 2][1],
                               ph[4 * jp + 3][0], ph[4 * jp + 3][1]};
            unsigned al1[4] = {pl[4 * jp + 2][0], pl[4 * jp + 2][1],
                               pl[4 * jp + 3][0], pl[4 * jp + 3][1]};
#pragma unroll
            for (int ct = 0; ct < 8; ct++) {
                const unsigned va = sb + 2 * AT_AS * 2 + ct * 1152 + jp * 64 + frag;
                unsigned vh4[4], vl4[4];
                ldm_x4(vh4, va);
                ldm_x4(vl4, va + AT_AS * 2);
                mma_bf16(o[ct], ah0, vh4[0], vh4[1]);
                mma_bf16(o[ct], ah0, vl4[0], vl4[1]);
                mma_bf16(o[ct], al0, vh4[0], vh4[1]);
                mma_bf16(o[ct], ah1, vh4[2], vh4[3]);
                mma_bf16(o[ct], ah1, vl4[2], vl4[3]);
                mma_bf16(o[ct], al1, vh4[2], vh4[3]);
            }
        }
        __syncthreads();
    }

    // ---- epilogue: normalize, split to bf16 hi/lo, write Oh/Ol ----
    float i0 = 1.f / l0, i1 = 1.f / l1;
    const long obase = ((long)(b * NQL + qt * 128 + w * 16)) * NIN + h * NDH;
#pragma unroll
    for (int ct = 0; ct < 8; ct++) {
        int cc = 8 * ct + 2 * t;
        __nv_bfloat162 H, L;
        split1(o[ct][0] * i0, H.x, L.x);
        split1(o[ct][1] * i0, H.y, L.y);
        long o0 = obase + (long)g * NIN + cc;
        *(__nv_bfloat162*)(Oh + o0) = H;
        *(__nv_bfloat162*)(Ol + o0) = L;
        split1(o[ct][2] * i1, H.x, L.x);
        split1(o[ct][3] * i1, H.y, L.y);
        long o1 = obase + (long)(g + 8) * NIN + cc;
        *(__nv_bfloat162*)(Oh + o1) = H;
        *(__nv_bfloat162*)(Ol + o1) = L;
    }
}

// ---------------------------------------------------------------------------
// Launch pipeline (graph-capturable: kernel launches only)
// ---------------------------------------------------------------------------
extern "C" void kernel_launch(void* const* d_in, const int* in_sizes, int n_in,
                              void* d_out, int out_size)
{
    (void)in_sizes; (void)n_in; (void)out_size;
    const float* x   = (const float*)d_in[0];
    const float* ctx = (const float*)d_in[1];
    const float* Wq  = (const float*)d_in[2];
    const float* Wk  = (const float*)d_in[3];
    const float* Wv  = (const float*)d_in[4];
    const float* Wo  = (const float*)d_in[5];
    const float* bo  = (const float*)d_in[6];
    float* out = (float*)d_out;

    __nv_bfloat16 *Xh, *Xl, *Ch, *Cl, *Qh, *Ql, *Kh, *Kl, *Vh, *Vl, *Oh, *Ol;
    __nv_bfloat16 *Wqh, *Wql, *Wkh, *Wkl, *Wvh, *Wvl, *Woh, *Wol;
    cudaGetSymbolAddress((void**)&Xh, g_Xh);  cudaGetSymbolAddress((void**)&Xl, g_Xl);
    cudaGetSymbolAddress((void**)&Ch, g_Ch);  cudaGetSymbolAddress((void**)&Cl, g_Cl);
    cudaGetSymbolAddress((void**)&Qh, g_Qh);  cudaGetSymbolAddress((void**)&Ql, g_Ql);
    cudaGetSymbolAddress((void**)&Kh, g_Kh);  cudaGetSymbolAddress((void**)&Kl, g_Kl);
    cudaGetSymbolAddress((void**)&Vh, g_Vh);  cudaGetSymbolAddress((void**)&Vl, g_Vl);
    cudaGetSymbolAddress((void**)&Oh, g_Oh);  cudaGetSymbolAddress((void**)&Ol, g_Ol);
    cudaGetSymbolAddress((void**)&Wqh, g_Wqh); cudaGetSymbolAddress((void**)&Wql, g_Wql);
    cudaGetSymbolAddress((void**)&Wkh, g_Wkh); cudaGetSymbolAddress((void**)&Wkl, g_Wkl);
    cudaGetSymbolAddress((void**)&Wvh, g_Wvh); cudaGetSymbolAddress((void**)&Wvl, g_Wvl);
    cudaGetSymbolAddress((void**)&Woh, g_Woh); cudaGetSymbolAddress((void**)&Wol, g_Wol);

    cudaFuncSetAttribute(gemm3_kernel<0>,
                         cudaFuncAttributeMaxDynamicSharedMemorySize, G3_SMEM);
    cudaFuncSetAttribute(gemm3_kernel<1>,
                         cudaFuncAttributeMaxDynamicSharedMemorySize, G3_SMEM);
    cudaFuncSetAttribute(gemm3_kernel<2>,
                         cudaFuncAttributeMaxDynamicSharedMemorySize, G3_SMEM);
    cudaFuncSetAttribute(attn_mma_kernel,
                         cudaFuncAttributeMaxDynamicSharedMemorySize, AT_SMEM);

    const int MTOK = NB * NQL;   // 8192 token rows

    // Input & weight hi/lo splits
    const int nx4 = (MTOK * NQD) / 4;
    const int nc4 = (MTOK * NCD) / 4;
    split_kernel<<<(nx4 + 255) / 256, 256>>>(x,   Xh, Xl, nx4);
    split_kernel<<<(nc4 + 255) / 256, 256>>>(ctx, Ch, Cl, nc4);
    dim3 wb(32, 8);
    wsplit_kernel<<<dim3(NQD / 32, NIN / 32), wb>>>(Wq, Wqh, Wql, NQD, NIN);
    wsplit_kernel<<<dim3(NCD / 32, NIN / 32), wb>>>(Wk, Wkh, Wkl, NCD, NIN);
    wsplit_kernel<<<dim3(NCD / 32, NIN / 32), wb>>>(Wv, Wvh, Wvl, NCD, NIN);
    wsplit_kernel<<<dim3(NIN / 32, NQD / 32), wb>>>(Wo, Woh, Wol, NIN, NQD);

    // Projections on tensor cores (bf16x3), epilogue-fused output formats
    dim3 gp(NIN / 128, MTOK / 128);
    gemm3_kernel<1><<<gp, 256, G3_SMEM>>>(Xh, Xl, Wqh, Wql, nullptr, nullptr,
                                          Qh, Ql, MTOK, NIN, NQD, ATTN_SCALE);
    gemm3_kernel<1><<<gp, 256, G3_SMEM>>>(Ch, Cl, Wkh, Wkl, nullptr, nullptr,
                                          Kh, Kl, MTOK, NIN, NCD, 1.0f);
    gemm3_kernel<2><<<gp, 256, G3_SMEM>>>(Ch, Cl, Wvh, Wvl, nullptr, nullptr,
                                          Vh, Vl, MTOK, NIN, NCD, 1.0f);

    // Flash attention on tensor cores (128-q tiles; emits bf16-split O)
    dim3 ga(NQL / 128, NH, NB);
    attn_mma_kernel<<<ga, 256, AT_SMEM>>>(Qh, Ql, Kh, Kl, Vh, Vl, Oh, Ol);

    // Output projection with bias (fp32 result)
    dim3 go(NQD / 128, MTOK / 128);
    gemm3_kernel<0><<<go, 256, G3_SMEM>>>(Oh, Ol, Woh, Wol, bo, out,
                                          nullptr, nullptr, MTOK, NQD, NIN, 1.0f);
}